// round 7
// baseline (speedup 1.0000x reference)
#include <cuda_runtime.h>
#include <math.h>

// x, x_r : (1, 3, 32, 512, 512) float32
// size=64 -> hc=wc=32 ; 16x16 patches per frame ; t=32
// patch mean = sum(|x - x_r|) / (2*3072) ; out = log(mean_t(max_patches))
// Deferred scaling: out = log( sum_t(max_p sum|dx|) / (32*6144) )
//
// Single-wave layout: 1024 CTAs x 256 threads, ONE PATCH PER WARP
// (1024 CTAs * 8 warps = 8192 patches). 1024 < 152 SMs * 8 CTAs -> exactly
// one wave, eliminating ~5.7 wave transitions of the previous 8192-CTA grid.

#define T_DIM 32
#define NPATCH 8192
#define NCTA 1024
#define HW 512
#define TSTRIDE (512u * 512u)
#define CSTRIDE (32u * 512u * 512u)

// Per-frame running max as float-bits-in-int (values >= 0 so int order ==
// float order; 0-init implements the max(.,0) clamp). Re-armed by the
// finalizing CTA so graph replays are deterministic.
__device__ int          g_frame_max[T_DIM];
__device__ unsigned int g_done_count;

__device__ __forceinline__ float4 ldcs4(const float* p) {
    float4 v;
    asm volatile("ld.global.cs.v4.f32 {%0,%1,%2,%3}, [%4];"
                 : "=f"(v.x), "=f"(v.y), "=f"(v.z), "=f"(v.w) : "l"(p));
    return v;
}

__global__ __launch_bounds__(256, 8)
void patch_loss_kernel(const float* __restrict__ x, const float* __restrict__ xr,
                       float* __restrict__ out) {
    const int wid  = threadIdx.x >> 5;
    const int lane = threadIdx.x & 31;

    const int p  = (blockIdx.x << 3) | wid;   // warp's patch: t*256 + ph*16 + pw
    const int t  = p >> 8;
    const int ph = (p >> 4) & 15;
    const int pw = p & 15;

    // lane covers (row = step*4 + lane/8, col4 = (lane%8)*4) of the 32x32 patch
    const size_t base = (size_t)t * TSTRIDE
                      + (size_t)(ph * 32 + (lane >> 3)) * HW
                      + (size_t)(pw * 32 + ((lane & 7) << 2));

    float acc = 0.0f;
    // 3 channels x 8 row-steps = 24 float4-pairs per lane (3072 floats/patch/tensor)
    #pragma unroll
    for (int i = 0; i < 24; ++i) {
        const int c = i >> 3;
        const int r = (i & 7) << 2;
        const size_t idx = base + (size_t)c * CSTRIDE + (size_t)r * HW;
        const float4 a = ldcs4(x  + idx);
        const float4 b = ldcs4(xr + idx);
        acc += fabsf(a.x - b.x) + fabsf(a.y - b.y)
             + fabsf(a.z - b.z) + fabsf(a.w - b.w);
    }

    // warp-local patch reduction (no smem, no block barrier on the hot path)
    #pragma unroll
    for (int o = 16; o > 0; o >>= 1)
        acc += __shfl_xor_sync(0xFFFFFFFFu, acc, o);

    if (lane == 0) {
        // REDG max (no return), L2-side
        asm volatile("red.global.max.s32 [%0], %1;"
                     :: "l"(&g_frame_max[t]), "r"(__float_as_int(acc)) : "memory");
    }

    __syncthreads();   // all 8 warps' REDGs issued before this CTA's ticket

    if (threadIdx.x < 32) {
        unsigned int prev = 0;
        if (lane == 0) {
            // release orders the REDGs above without an L1-flushing full fence
            asm volatile("atom.release.gpu.global.add.u32 %0, [%1], 1;"
                         : "=r"(prev) : "l"(&g_done_count) : "memory");
        }
        prev = __shfl_sync(0xFFFFFFFFu, prev, 0);

        if (prev == NCTA - 1) {                         // last CTA: finalize
            asm volatile("fence.acq_rel.gpu;" ::: "memory");
            float sum = __int_as_float(__ldcg(&g_frame_max[lane]));
            #pragma unroll
            for (int o = 16; o > 0; o >>= 1)
                sum += __shfl_xor_sync(0xFFFFFFFFu, sum, o);
            if (lane == 0) {
                *out = logf(sum / (32.0f * 6144.0f));
                g_done_count = 0u;                      // re-arm for next replay
            }
            __syncwarp();
            g_frame_max[lane] = 0;                      // re-arm (after reads)
        }
    }
}

extern "C" void kernel_launch(void* const* d_in, const int* in_sizes, int n_in,
                              void* d_out, int out_size) {
    const float* x  = (const float*)d_in[0];
    const float* xr = (const float*)d_in[1];
    patch_loss_kernel<<<NCTA, 256>>>(x, xr, (float*)d_out);
}